// round 5
// baseline (speedup 1.0000x reference)
#include <cuda_runtime.h>
#include <math.h>

#define BS 16
#define TT 20
#define NN 512
#define EE 64
#define LL 8
#define STEPS 12
#define NROWS 19   // rows of skill_seq used as S-row indices (0..18)

// ---------------- scratch (device globals; no allocation allowed) ----------
__device__ float g_S[BS * 2 * NROWS * NN];   // S[b][k][r][n] = adj[k,b,sh_r,n] + adj2[k,b,sh_r,n]
__device__ float g_hA[BS * NN * EE];
__device__ float g_hB[BS * NN * EE];
__device__ float g_ew[STEPS * BS * LL];      // exp(-dtw)

// ---------------- helpers --------------------------------------------------
__device__ __forceinline__ float tanh_fast(float x) {
    // 1 - 2/(e^{2x}+1); saturates correctly at +/-1, abs err ~1e-7
    float e = __expf(2.0f * x);
    return 1.0f - __fdividef(2.0f, e + 1.0f);
}

__device__ __forceinline__ float warp_sum(float v) {
#pragma unroll
    for (int o = 16; o > 0; o >>= 1) v += __shfl_xor_sync(0xffffffffu, v, o);
    return v;
}

// ---------------- hidden0 --------------------------------------------------
// grid (BS, NN/4), block 256 = 4 nodes x 64 e
__global__ void k_init_hidden(const int* __restrict__ skill,
                              const int* __restrict__ label,
                              const float* __restrict__ emb,
                              float* __restrict__ hid) {
    int b = blockIdx.x;
    int n = blockIdx.y * 4 + (threadIdx.x >> 6);
    int e = threadIdx.x & 63;
    float v = 0.0f;
    // last occurrence of skill n in first L positions contributes emb*lp
#pragma unroll
    for (int l = LL - 1; l >= 0; --l) {
        if (skill[b * TT + l] == n) {
            float lp = (label[b * TT + l] == 0) ? -1.0f : 1.0f;
            v = emb[n * EE + e] * lp;
            break;
        }
    }
    hid[(b * NN + n) * EE + e] = v;
}

// ---------------- exp(-dtw) ------------------------------------------------
__global__ void k_ew(const int* __restrict__ timeq) {
    int idx = blockIdx.x * blockDim.x + threadIdx.x;
    if (idx >= STEPS * BS * LL) return;
    int l = idx % LL;
    int b = (idx / LL) % BS;
    int t = idx / (LL * BS);
    float d = fabsf((float)timeq[b * TT + t + l] - (float)timeq[b * TT + t + LL]) + 1e-6f;
    float dtw = logf(d) / logf(5.0f);
    g_ew[idx] = expf(-dtw);
}

// ---------------- S rows: adj + adj@adj/N, only the 19 needed rows ---------
// grid (4 nchunk, 2 k, BS b), block 128 (one n per thread)
__global__ void k_S(const int* __restrict__ skill, const float* __restrict__ adj) {
    int chunk = blockIdx.x, k = blockIdx.y, b = blockIdx.z;
    int n = chunk * 128 + threadIdx.x;

    __shared__ float arows[NROWS][NN];
    __shared__ int rowskill[NROWS];
    if (threadIdx.x < NROWS) rowskill[threadIdx.x] = skill[b * TT + threadIdx.x];
    __syncthreads();

    const float* A = adj + ((size_t)k * BS + b) * NN * NN;
    for (int idx = threadIdx.x; idx < NROWS * NN; idx += 128) {
        int r = idx >> 9;
        int j = idx & 511;
        arows[r][j] = A[rowskill[r] * NN + j];
    }
    __syncthreads();

    float acc[NROWS];
#pragma unroll
    for (int r = 0; r < NROWS; r++) acc[r] = 0.0f;

#pragma unroll 4
    for (int j = 0; j < NN; j++) {
        float c = A[j * NN + n];
#pragma unroll
        for (int r = 0; r < NROWS; r++) acc[r] += arows[r][j] * c;
    }

    const float inv = 1.0f / (float)NN;
#pragma unroll
    for (int r = 0; r < NROWS; r++) {
        g_S[(((size_t)b * 2 + k) * NROWS + r) * NN + n] = arows[r][n] + acc[r] * inv;
    }
}

// ---------------- f-network at target node (one warp) ----------------------
__device__ __forceinline__ void fnet_warp(
    float x0, float x1, int lane, float* sx,
    const float* __restrict__ fw1, const float* __restrict__ fb1,
    const float* __restrict__ ln1g, const float* __restrict__ ln1b,
    const float* __restrict__ fw2, const float* __restrict__ fb2,
    const float* __restrict__ ln2g, const float* __restrict__ ln2b,
    const float* __restrict__ fw3, const float* __restrict__ fb3,
    float* __restrict__ outp) {

    __syncwarp();
    sx[lane] = x0; sx[lane + 32] = x1;
    __syncwarp();
    float t0 = fb1[lane], t1 = fb1[lane + 32];
#pragma unroll 8
    for (int f = 0; f < 64; f++) {
        float v = sx[f];
        t0 += v * fw1[lane * 64 + f];
        t1 += v * fw1[(lane + 32) * 64 + f];
    }
    float h0 = x0 + (t0 > 0.0f ? t0 : 0.01f * t0);
    float h1 = x1 + (t1 > 0.0f ? t1 : 0.01f * t1);

    float m = warp_sum(h0 + h1) * (1.0f / 64.0f);
    float d0 = h0 - m, d1 = h1 - m;
    float var = warp_sum(d0 * d0 + d1 * d1) * (1.0f / 64.0f);
    float r = rsqrtf(var + 1e-5f);
    float y0 = d0 * r * ln1g[lane] + ln1b[lane];
    float y1 = d1 * r * ln1g[lane + 32] + ln1b[lane + 32];

    __syncwarp();
    sx[lane] = y0; sx[lane + 32] = y1;
    __syncwarp();
    t0 = fb2[lane]; t1 = fb2[lane + 32];
#pragma unroll 8
    for (int f = 0; f < 64; f++) {
        float v = sx[f];
        t0 += v * fw2[lane * 64 + f];
        t1 += v * fw2[(lane + 32) * 64 + f];
    }
    h0 += (t0 > 0.0f ? t0 : 0.01f * t0);
    h1 += (t1 > 0.0f ? t1 : 0.01f * t1);

    m = warp_sum(h0 + h1) * (1.0f / 64.0f);
    d0 = h0 - m; d1 = h1 - m;
    var = warp_sum(d0 * d0 + d1 * d1) * (1.0f / 64.0f);
    r = rsqrtf(var + 1e-5f);
    float z0 = d0 * r * ln2g[lane] + ln2b[lane];
    float z1 = d1 * r * ln2g[lane + 32] + ln2b[lane + 32];

    float l0 = warp_sum(z0 * fw3[lane] + z1 * fw3[lane + 32]);
    float l1 = warp_sum(z0 * fw3[64 + lane] + z1 * fw3[64 + lane + 32]);
    if (lane == 0) {
        l0 += fb3[0]; l1 += fb3[1];
        *outp = 1.0f / (1.0f + expf(l0 - l1));   // softmax class-1 prob
    }
    __syncwarp();
}

// ---------------- fused step kernel ----------------------------------------
// grid (16 ngroups, BS b), block 256 = 8 warps, each warp 4 nodes.
// smem layout (floats): W1a 4160 | W1b 4160 | W2 4160 | M1 4096 | A 512 |
//                       HH 512 | HB 512 | B2 64 | EW 8 | SH 8(int)
#define SMEM_FLOATS 18192
#define SMEM_BYTES  (SMEM_FLOATS * 4)

__global__ __launch_bounds__(256) void k_step(
    const float* __restrict__ hcur, float* __restrict__ hnext, int t,
    const int* __restrict__ skill,
    const float* __restrict__ fc1w, const float* __restrict__ fc1b,
    const float* __restrict__ fc2w, const float* __restrict__ fc2b,
    const float* __restrict__ fw1, const float* __restrict__ fb1,
    const float* __restrict__ ln1g, const float* __restrict__ ln1b,
    const float* __restrict__ fw2, const float* __restrict__ fb2,
    const float* __restrict__ ln2g, const float* __restrict__ ln2b,
    const float* __restrict__ fw3, const float* __restrict__ fb3,
    float* __restrict__ out) {

    extern __shared__ float s[];
    float* sW1a = s;                 // [f][e] stride 65
    float* sW1b = s + 4160;
    float* sW2  = s + 8320;
    float* sM1  = s + 12480;         // per-warp [8 l][64 e]
    float* sA   = s + 16576;         // [8 l][64 e]
    float* sHH  = s + 17088;         // per-warp hidden row (A phase)
    float* sHB  = s + 17600;         // per-warp hidden row (B phase) / fnet scratch
    float* sB2  = s + 18112;
    float* sEW  = s + 18176;
    int*   sSH  = (int*)(s + 18184);

    int b = blockIdx.y;
    int g = blockIdx.x;
    int tid = threadIdx.x;
    int w = tid >> 5;
    int lane = tid & 31;

    // --- load weights (coalesced read, transposed conflict-free write) ---
    for (int idx = tid; idx < 64 * 128; idx += 256) {
        int e = idx >> 7, c = idx & 127;
        float v = fc1w[idx];
        if (c < 64) sW1a[c * 65 + e] = v;
        else        sW1b[(c - 64) * 65 + e] = v;
    }
    for (int idx = tid; idx < 64 * 64; idx += 256) {
        int e = idx >> 6, f = idx & 63;
        sW2[f * 65 + e] = fc2w[idx];
    }
    if (tid < 64) sB2[tid] = fc2b[tid];
    if (tid < 8) {
        sEW[tid] = g_ew[(t * BS + b) * LL + tid];
        sSH[tid] = skill[b * TT + t + tid];
    }
    __syncthreads();

    // --- phase 1: warp w computes A[w][:] = hh[w] @ W1a^T + b1 ---
    {
        int sl = sSH[w];
        float h0 = hcur[((b << 9) + sl) * EE + lane];
        float h1 = hcur[((b << 9) + sl) * EE + lane + 32];
        sHH[w * 64 + lane] = h0;
        sHH[w * 64 + lane + 32] = h1;
        __syncwarp();
        float a0 = fc1b[lane], a1 = fc1b[lane + 32];
#pragma unroll 8
        for (int f = 0; f < 64; f++) {
            float v = sHH[w * 64 + f];
            a0 += v * sW1a[f * 65 + lane];
            a1 += v * sW1a[f * 65 + lane + 32];
        }
        sA[w * 64 + lane] = a0;
        sA[w * 64 + lane + 32] = a1;
    }
    __syncthreads();

    int tgt = __ldg(&skill[b * TT + t + LL]);
    float* myM1 = sM1 + w * 512;
    float* mysx = sHB + w * 64;

#pragma unroll 1
    for (int i = 0; i < 4; i++) {
        int n = (g << 5) + (w << 2) + i;

        // hidden row of this node
        float h0 = hcur[((b << 9) + n) * EE + lane];
        float h1 = hcur[((b << 9) + n) * EE + lane + 32];
        __syncwarp();
        mysx[lane] = h0;
        mysx[lane + 32] = h1;

        // S rows (uniform loads, prefetched here; used in epilogue)
        float wr[16];
#pragma unroll
        for (int k = 0; k < 2; k++)
#pragma unroll
            for (int l = 0; l < 8; l++)
                wr[k * 8 + l] = __ldg(&g_S[((((size_t)b << 1) + k) * NROWS + (t + l)) * NN + n]);

        __syncwarp();
        // B = hidden[n] @ W1b^T
        float B0 = 0.0f, B1 = 0.0f;
#pragma unroll 8
        for (int f = 0; f < 64; f++) {
            float v = mysx[f];
            B0 += v * sW1b[f * 65 + lane];
            B1 += v * sW1b[f * 65 + lane + 32];
        }

        // msg1 = tanh(A + B)
#pragma unroll
        for (int l = 0; l < 8; l++) {
            myM1[l * 64 + lane]      = tanh_fast(sA[l * 64 + lane] + B0);
            myM1[l * 64 + lane + 32] = tanh_fast(sA[l * 64 + lane + 32] + B1);
        }
        __syncwarp();

        // fc2 for all 8 l's at once
        float acc0[8], acc1[8];
#pragma unroll
        for (int l = 0; l < 8; l++) { acc0[l] = 0.0f; acc1[l] = 0.0f; }
#pragma unroll 4
        for (int f = 0; f < 64; f++) {
            float w0 = sW2[f * 65 + lane];
            float w1 = sW2[f * 65 + lane + 32];
#pragma unroll
            for (int l = 0; l < 8; l++) {
                float v = myM1[l * 64 + f];
                acc0[l] += w0 * v;
                acc1[l] += w1 * v;
            }
        }

        // msg2 = tanh(.+b2)*ew ; agg over l with S weights
        float b20 = sB2[lane], b21 = sB2[lane + 32];
        float ag00 = 0, ag01 = 0, ag10 = 0, ag11 = 0;
#pragma unroll
        for (int l = 0; l < 8; l++) {
            float ewl = sEW[l];
            float m0 = tanh_fast(acc0[l] + b20) * ewl;
            float m1 = tanh_fast(acc1[l] + b21) * ewl;
            ag00 += wr[l] * m0;      ag01 += wr[l] * m1;
            ag10 += wr[8 + l] * m0;  ag11 += wr[8 + l] * m1;
        }

        // new_hidden = mean over k
        hnext[((b << 9) + n) * EE + lane]      = 0.5f * (ag00 + ag10);
        hnext[((b << 9) + n) * EE + lane + 32] = 0.5f * (ag01 + ag11);

        // prediction head only at the target node
        if (n == tgt) {
            fnet_warp(ag00, ag01, lane, mysx, fw1, fb1, ln1g, ln1b,
                      fw2, fb2, ln2g, ln2b, fw3, fb3,
                      &out[(t * BS + b) * 2 + 0]);
            fnet_warp(ag10, ag11, lane, mysx, fw1, fb1, ln1g, ln1b,
                      fw2, fb2, ln2g, ln2b, fw3, fb3,
                      &out[(t * BS + b) * 2 + 1]);
        }
        __syncwarp();
    }
}

// ---------------- launch ----------------------------------------------------
extern "C" void kernel_launch(void* const* d_in, const int* in_sizes, int n_in,
                              void* d_out, int out_size) {
    const int*   skill = (const int*)d_in[0];
    const int*   timeq = (const int*)d_in[1];
    const int*   label = (const int*)d_in[2];
    const float* adj   = (const float*)d_in[3];
    const float* emb   = (const float*)d_in[4];
    const float* fc1w  = (const float*)d_in[5];
    const float* fc1b  = (const float*)d_in[6];
    const float* fc2w  = (const float*)d_in[7];
    const float* fc2b  = (const float*)d_in[8];
    const float* fw1   = (const float*)d_in[9];
    const float* fb1   = (const float*)d_in[10];
    const float* ln1g  = (const float*)d_in[11];
    const float* ln1b  = (const float*)d_in[12];
    const float* fw2   = (const float*)d_in[13];
    const float* fb2   = (const float*)d_in[14];
    const float* ln2g  = (const float*)d_in[15];
    const float* ln2b  = (const float*)d_in[16];
    const float* fw3   = (const float*)d_in[17];
    const float* fb3   = (const float*)d_in[18];
    float* out = (float*)d_out;

    cudaFuncSetAttribute(k_step, cudaFuncAttributeMaxDynamicSharedMemorySize, SMEM_BYTES);

    float *hA, *hB;
    cudaGetSymbolAddress((void**)&hA, g_hA);
    cudaGetSymbolAddress((void**)&hB, g_hB);

    k_init_hidden<<<dim3(BS, NN / 4), 256>>>(skill, label, emb, hA);
    k_ew<<<3, 512>>>(timeq);
    k_S<<<dim3(4, 2, BS), 128>>>(skill, adj);

    for (int t = 0; t < STEPS; t++) {
        const float* hc = (t & 1) ? hB : hA;
        float*       hn = (t & 1) ? hA : hB;
        k_step<<<dim3(16, BS), 256, SMEM_BYTES>>>(
            hc, hn, t, skill,
            fc1w, fc1b, fc2w, fc2b,
            fw1, fb1, ln1g, ln1b, fw2, fb2, ln2g, ln2b, fw3, fb3,
            out);
    }
}

// round 6
// speedup vs baseline: 1.0057x; 1.0057x over previous
#include <cuda_runtime.h>
#include <math.h>

#define BS 16
#define TT 20
#define NN 512
#define EE 64
#define LL 8
#define STEPS 12
#define NROWS 19   // rows of skill_seq used as S-row indices (0..18)

// ---------------- scratch (device globals; no allocation allowed) ----------
__device__ float g_S[BS * 2 * NROWS * NN];   // S[b][k][r][n] = adj[k,b,sh_r,n] + adj2[k,b,sh_r,n]
__device__ float g_hA[BS * NN * EE];
__device__ float g_hB[BS * NN * EE];
__device__ float g_ew[STEPS * BS * LL];      // exp(-dtw)

// ---------------- helpers --------------------------------------------------
__device__ __forceinline__ float tanh_fast(float x) {
    // 1 - 2/(e^{2x}+1); saturates correctly at +/-1, abs err ~1e-7
    float e = __expf(2.0f * x);
    return 1.0f - __fdividef(2.0f, e + 1.0f);
}

__device__ __forceinline__ float warp_sum(float v) {
#pragma unroll
    for (int o = 16; o > 0; o >>= 1) v += __shfl_xor_sync(0xffffffffu, v, o);
    return v;
}

// packed f32x2 FMA: d = a*b + d   (sm_100+ PTX; SASS FFMA2)
__device__ __forceinline__ void fma2(unsigned long long& d,
                                     unsigned long long a,
                                     unsigned long long b) {
    asm("fma.rn.f32x2 %0, %1, %2, %0;" : "+l"(d) : "l"(a), "l"(b));
}
__device__ __forceinline__ float2 up2(unsigned long long p) {
    float2 r;
    asm("mov.b64 {%0,%1}, %2;" : "=f"(r.x), "=f"(r.y) : "l"(p));
    return r;
}
__device__ __forceinline__ float red2(unsigned long long p) {
    float2 r = up2(p);
    return r.x + r.y;
}

// ---------------- hidden0 --------------------------------------------------
// grid (BS, NN/4), block 256 = 4 nodes x 64 e
__global__ void k_init_hidden(const int* __restrict__ skill,
                              const int* __restrict__ label,
                              const float* __restrict__ emb,
                              float* __restrict__ hid) {
    int b = blockIdx.x;
    int n = blockIdx.y * 4 + (threadIdx.x >> 6);
    int e = threadIdx.x & 63;
    float v = 0.0f;
#pragma unroll
    for (int l = LL - 1; l >= 0; --l) {
        if (skill[b * TT + l] == n) {
            float lp = (label[b * TT + l] == 0) ? -1.0f : 1.0f;
            v = emb[n * EE + e] * lp;
            break;
        }
    }
    hid[(b * NN + n) * EE + e] = v;
}

// ---------------- exp(-dtw) ------------------------------------------------
__global__ void k_ew(const int* __restrict__ timeq) {
    int idx = blockIdx.x * blockDim.x + threadIdx.x;
    if (idx >= STEPS * BS * LL) return;
    int l = idx % LL;
    int b = (idx / LL) % BS;
    int t = idx / (LL * BS);
    float d = fabsf((float)timeq[b * TT + t + l] - (float)timeq[b * TT + t + LL]) + 1e-6f;
    float dtw = logf(d) / logf(5.0f);
    g_ew[idx] = expf(-dtw);
}

// ---------------- S rows: adj + adj@adj/N, only the 19 needed rows ---------
// grid (4 nchunk, 2 k, BS b), block 128 (one n per thread)
__global__ void k_S(const int* __restrict__ skill, const float* __restrict__ adj) {
    int chunk = blockIdx.x, k = blockIdx.y, b = blockIdx.z;
    int n = chunk * 128 + threadIdx.x;

    __shared__ float arows[NROWS][NN];
    __shared__ int rowskill[NROWS];
    if (threadIdx.x < NROWS) rowskill[threadIdx.x] = skill[b * TT + threadIdx.x];
    __syncthreads();

    const float* A = adj + ((size_t)k * BS + b) * NN * NN;
    for (int idx = threadIdx.x; idx < NROWS * NN; idx += 128) {
        int r = idx >> 9;
        int j = idx & 511;
        arows[r][j] = A[rowskill[r] * NN + j];
    }
    __syncthreads();

    float acc[NROWS];
#pragma unroll
    for (int r = 0; r < NROWS; r++) acc[r] = 0.0f;

#pragma unroll 4
    for (int j = 0; j < NN; j++) {
        float c = A[j * NN + n];
#pragma unroll
        for (int r = 0; r < NROWS; r++) acc[r] += arows[r][j] * c;
    }

    const float inv = 1.0f / (float)NN;
#pragma unroll
    for (int r = 0; r < NROWS; r++) {
        g_S[(((size_t)b * 2 + k) * NROWS + r) * NN + n] = arows[r][n] + acc[r] * inv;
    }
}

// ---------------- f-network at target node (one warp) ----------------------
__device__ __forceinline__ void fnet_warp(
    float x0, float x1, int lane, float* sx,
    const float* __restrict__ fw1, const float* __restrict__ fb1,
    const float* __restrict__ ln1g, const float* __restrict__ ln1b,
    const float* __restrict__ fw2, const float* __restrict__ fb2,
    const float* __restrict__ ln2g, const float* __restrict__ ln2b,
    const float* __restrict__ fw3, const float* __restrict__ fb3,
    float* __restrict__ outp) {

    __syncwarp();
    sx[lane] = x0; sx[lane + 32] = x1;
    __syncwarp();
    float t0 = fb1[lane], t1 = fb1[lane + 32];
#pragma unroll 8
    for (int f = 0; f < 64; f++) {
        float v = sx[f];
        t0 += v * fw1[lane * 64 + f];
        t1 += v * fw1[(lane + 32) * 64 + f];
    }
    float h0 = x0 + (t0 > 0.0f ? t0 : 0.01f * t0);
    float h1 = x1 + (t1 > 0.0f ? t1 : 0.01f * t1);

    float m = warp_sum(h0 + h1) * (1.0f / 64.0f);
    float d0 = h0 - m, d1 = h1 - m;
    float var = warp_sum(d0 * d0 + d1 * d1) * (1.0f / 64.0f);
    float r = rsqrtf(var + 1e-5f);
    float y0 = d0 * r * ln1g[lane] + ln1b[lane];
    float y1 = d1 * r * ln1g[lane + 32] + ln1b[lane + 32];

    __syncwarp();
    sx[lane] = y0; sx[lane + 32] = y1;
    __syncwarp();
    t0 = fb2[lane]; t1 = fb2[lane + 32];
#pragma unroll 8
    for (int f = 0; f < 64; f++) {
        float v = sx[f];
        t0 += v * fw2[lane * 64 + f];
        t1 += v * fw2[(lane + 32) * 64 + f];
    }
    h0 += (t0 > 0.0f ? t0 : 0.01f * t0);
    h1 += (t1 > 0.0f ? t1 : 0.01f * t1);

    m = warp_sum(h0 + h1) * (1.0f / 64.0f);
    d0 = h0 - m; d1 = h1 - m;
    var = warp_sum(d0 * d0 + d1 * d1) * (1.0f / 64.0f);
    r = rsqrtf(var + 1e-5f);
    float z0 = d0 * r * ln2g[lane] + ln2b[lane];
    float z1 = d1 * r * ln2g[lane + 32] + ln2b[lane + 32];

    float l0 = warp_sum(z0 * fw3[lane] + z1 * fw3[lane + 32]);
    float l1 = warp_sum(z0 * fw3[64 + lane] + z1 * fw3[64 + lane + 32]);
    if (lane == 0) {
        l0 += fb3[0]; l1 += fb3[1];
        *outp = 1.0f / (1.0f + expf(l0 - l1));   // softmax class-1 prob
    }
    __syncwarp();
}

// ---------------- fused step kernel ----------------------------------------
// grid (32 ngroups, BS b), block 256 = 8 warps, each warp 2 sequential nodes.
// Weight layout: row-major per output e with row stride 68 floats
//   -> lane-e LDS.128 of its own row is exactly crossbar-rate (no excess
//      conflict: 4-lane groups tile all 32 banks, 4 cyc = 512B/128B floor),
//      and gives two packed f32x2 operands over f-pairs for FFMA2.
// smem (floats): W1a 4352 | W1b 4352 | W2 4352 | M1 4096 | A 512 | HH 512 |
//                HB 512 | B2 64 | EW 8 | SH 8
#define SW_STRIDE 68
#define SMEM_FLOATS 18768
#define SMEM_BYTES  (SMEM_FLOATS * 4)

__global__ __launch_bounds__(256) void k_step(
    const float* __restrict__ hcur, float* __restrict__ hnext, int t,
    const int* __restrict__ skill,
    const float* __restrict__ fc1w, const float* __restrict__ fc1b,
    const float* __restrict__ fc2w, const float* __restrict__ fc2b,
    const float* __restrict__ fw1, const float* __restrict__ fb1,
    const float* __restrict__ ln1g, const float* __restrict__ ln1b,
    const float* __restrict__ fw2, const float* __restrict__ fb2,
    const float* __restrict__ ln2g, const float* __restrict__ ln2b,
    const float* __restrict__ fw3, const float* __restrict__ fb3,
    float* __restrict__ out) {

    extern __shared__ float s[];
    float* sW1a = s;                  // [e][f] stride 68
    float* sW1b = s + 4352;           // [e][f] stride 68
    float* sW2  = s + 8704;           // [e][f] stride 68
    float* sM1  = s + 13056;          // per-warp [8 l][64 f]
    float* sA   = s + 17152;          // [8 l][64 e]
    float* sHH  = s + 17664;          // per-warp hh row (phase 1)
    float* sHB  = s + 18176;          // per-warp hidden row / fnet scratch
    float* sB2  = s + 18688;
    float* sEW  = s + 18752;
    int*   sSH  = (int*)(s + 18760);

    int b = blockIdx.y;
    int g = blockIdx.x;
    int tid = threadIdx.x;
    int w = tid >> 5;
    int lane = tid & 31;

    // --- load weights: coalesced gmem read, e-row-major smem (stride 68) ---
    for (int idx = tid; idx < 64 * 128; idx += 256) {
        int e = idx >> 7, c = idx & 127;
        float v = fc1w[idx];
        if (c < 64) sW1a[e * SW_STRIDE + c] = v;
        else        sW1b[e * SW_STRIDE + (c - 64)] = v;
    }
    for (int idx = tid; idx < 64 * 64; idx += 256) {
        int e = idx >> 6, f = idx & 63;
        sW2[e * SW_STRIDE + f] = fc2w[idx];
    }
    if (tid < 64) sB2[tid] = fc2b[tid];
    if (tid < 8) {
        sEW[tid] = g_ew[(t * BS + b) * LL + tid];
        sSH[tid] = skill[b * TT + t + tid];
    }
    __syncthreads();

    const unsigned long long* w1aA =
        (const unsigned long long*)(sW1a + lane * SW_STRIDE);
    const unsigned long long* w1aB =
        (const unsigned long long*)(sW1a + (lane + 32) * SW_STRIDE);
    const unsigned long long* w1bA =
        (const unsigned long long*)(sW1b + lane * SW_STRIDE);
    const unsigned long long* w1bB =
        (const unsigned long long*)(sW1b + (lane + 32) * SW_STRIDE);
    const unsigned long long* w2A =
        (const unsigned long long*)(sW2 + lane * SW_STRIDE);
    const unsigned long long* w2B =
        (const unsigned long long*)(sW2 + (lane + 32) * SW_STRIDE);

    // --- phase 1: warp w computes A[w][:] = hh[w] @ W1a^T + b1 (packed) ---
    {
        int sl = sSH[w];
        sHH[w * 64 + lane]      = hcur[((b << 9) + sl) * EE + lane];
        sHH[w * 64 + lane + 32] = hcur[((b << 9) + sl) * EE + lane + 32];
        __syncwarp();
        unsigned long long a0 = 0ull, a1 = 0ull;
        const unsigned long long* hv = (const unsigned long long*)(sHH + w * 64);
#pragma unroll
        for (int fp = 0; fp < 16; fp++) {
            unsigned long long m01 = hv[2 * fp], m23 = hv[2 * fp + 1];
            fma2(a0, m01, w1aA[2 * fp]); fma2(a0, m23, w1aA[2 * fp + 1]);
            fma2(a1, m01, w1aB[2 * fp]); fma2(a1, m23, w1aB[2 * fp + 1]);
        }
        sA[w * 64 + lane]      = red2(a0) + fc1b[lane];
        sA[w * 64 + lane + 32] = red2(a1) + fc1b[lane + 32];
    }
    __syncthreads();

    int tgt = __ldg(&skill[b * TT + t + LL]);
    float* myM1 = sM1 + w * 512;
    float* mysx = sHB + w * 64;
    const unsigned long long* mv = (const unsigned long long*)myM1;
    const unsigned long long* hv = (const unsigned long long*)mysx;

#pragma unroll 1
    for (int i = 0; i < 2; i++) {
        int n = (g << 4) + (w << 1) + i;

        // hidden row of this node -> smem for packed broadcast
        mysx[lane]      = hcur[((b << 9) + n) * EE + lane];
        mysx[lane + 32] = hcur[((b << 9) + n) * EE + lane + 32];
        __syncwarp();

        // B = hidden[n] @ W1b^T  (f-pair packed)
        unsigned long long bp0 = 0ull, bp1 = 0ull;
#pragma unroll
        for (int fp = 0; fp < 16; fp++) {
            unsigned long long m01 = hv[2 * fp], m23 = hv[2 * fp + 1];
            fma2(bp0, m01, w1bA[2 * fp]); fma2(bp0, m23, w1bA[2 * fp + 1]);
            fma2(bp1, m01, w1bB[2 * fp]); fma2(bp1, m23, w1bB[2 * fp + 1]);
        }
        float B0 = red2(bp0), B1 = red2(bp1);

        // msg1 = tanh(A + B)
#pragma unroll
        for (int l = 0; l < 8; l++) {
            myM1[l * 64 + lane]      = tanh_fast(sA[l * 64 + lane] + B0);
            myM1[l * 64 + lane + 32] = tanh_fast(sA[l * 64 + lane + 32] + B1);
        }
        __syncwarp();

        // fc2 for all 8 l's, f-pair packed FFMA2
        unsigned long long acc0[8], acc1[8];
#pragma unroll
        for (int l = 0; l < 8; l++) { acc0[l] = 0ull; acc1[l] = 0ull; }
#pragma unroll 4
        for (int fp = 0; fp < 16; fp++) {
            unsigned long long wa01 = w2A[2 * fp], wa23 = w2A[2 * fp + 1];
            unsigned long long wb01 = w2B[2 * fp], wb23 = w2B[2 * fp + 1];
#pragma unroll
            for (int l = 0; l < 8; l++) {
                unsigned long long m01 = mv[l * 32 + 2 * fp];
                unsigned long long m23 = mv[l * 32 + 2 * fp + 1];
                fma2(acc0[l], m01, wa01); fma2(acc0[l], m23, wa23);
                fma2(acc1[l], m01, wb01); fma2(acc1[l], m23, wb23);
            }
        }

        // S rows (uniform L2-resident loads, full MLP)
        float wr[16];
#pragma unroll
        for (int k = 0; k < 2; k++)
#pragma unroll
            for (int l = 0; l < 8; l++)
                wr[k * 8 + l] = __ldg(&g_S[((((size_t)b << 1) + k) * NROWS + (t + l)) * NN + n]);

        // msg2 = tanh(.+b2)*ew ; agg over l with S weights
        float b20 = sB2[lane], b21 = sB2[lane + 32];
        float ag00 = 0, ag01 = 0, ag10 = 0, ag11 = 0;
#pragma unroll
        for (int l = 0; l < 8; l++) {
            float ewl = sEW[l];
            float m0 = tanh_fast(red2(acc0[l]) + b20) * ewl;
            float m1 = tanh_fast(red2(acc1[l]) + b21) * ewl;
            ag00 += wr[l] * m0;      ag01 += wr[l] * m1;
            ag10 += wr[8 + l] * m0;  ag11 += wr[8 + l] * m1;
        }

        // new_hidden = mean over k
        hnext[((b << 9) + n) * EE + lane]      = 0.5f * (ag00 + ag10);
        hnext[((b << 9) + n) * EE + lane + 32] = 0.5f * (ag01 + ag11);

        // prediction head only at the target node
        if (n == tgt) {
            fnet_warp(ag00, ag01, lane, mysx, fw1, fb1, ln1g, ln1b,
                      fw2, fb2, ln2g, ln2b, fw3, fb3,
                      &out[(t * BS + b) * 2 + 0]);
            fnet_warp(ag10, ag11, lane, mysx, fw1, fb1, ln1g, ln1b,
                      fw2, fb2, ln2g, ln2b, fw3, fb3,
                      &out[(t * BS + b) * 2 + 1]);
        }
        __syncwarp();
    }
}

// ---------------- launch ----------------------------------------------------
extern "C" void kernel_launch(void* const* d_in, const int* in_sizes, int n_in,
                              void* d_out, int out_size) {
    const int*   skill = (const int*)d_in[0];
    const int*   timeq = (const int*)d_in[1];
    const int*   label = (const int*)d_in[2];
    const float* adj   = (const float*)d_in[3];
    const float* emb   = (const float*)d_in[4];
    const float* fc1w  = (const float*)d_in[5];
    const float* fc1b  = (const float*)d_in[6];
    const float* fc2w  = (const float*)d_in[7];
    const float* fc2b  = (const float*)d_in[8];
    const float* fw1   = (const float*)d_in[9];
    const float* fb1   = (const float*)d_in[10];
    const float* ln1g  = (const float*)d_in[11];
    const float* ln1b  = (const float*)d_in[12];
    const float* fw2   = (const float*)d_in[13];
    const float* fb2   = (const float*)d_in[14];
    const float* ln2g  = (const float*)d_in[15];
    const float* ln2b  = (const float*)d_in[16];
    const float* fw3   = (const float*)d_in[17];
    const float* fb3   = (const float*)d_in[18];
    float* out = (float*)d_out;

    cudaFuncSetAttribute(k_step, cudaFuncAttributeMaxDynamicSharedMemorySize, SMEM_BYTES);

    float *hA, *hB;
    cudaGetSymbolAddress((void**)&hA, g_hA);
    cudaGetSymbolAddress((void**)&hB, g_hB);

    k_init_hidden<<<dim3(BS, NN / 4), 256>>>(skill, label, emb, hA);
    k_ew<<<3, 512>>>(timeq);
    k_S<<<dim3(4, 2, BS), 128>>>(skill, adj);

    for (int t = 0; t < STEPS; t++) {
        const float* hc = (t & 1) ? hB : hA;
        float*       hn = (t & 1) ? hA : hB;
        k_step<<<dim3(32, BS), 256, SMEM_BYTES>>>(
            hc, hn, t, skill,
            fc1w, fc1b, fc2w, fc2b,
            fw1, fb1, ln1g, ln1b, fw2, fb2, ln2g, ln2b, fw3, fb3,
            out);
    }
}